// round 3
// baseline (speedup 1.0000x reference)
#include <cuda_runtime.h>
#include <cstdint>

#define N_NODES_MAX 100000
#define E_MAX 600000
#define CH 128

// Scratch (allocation-free rule: __device__ globals)
__device__ float g_h[N_NODES_MAX * CH];
__device__ int   g_deg[N_NODES_MAX];
__device__ float g_dinv[N_NODES_MAX];
__device__ int   g_off[N_NODES_MAX + 1];
__device__ int   g_cur[N_NODES_MAX];
__device__ int   g_srcs[E_MAX];

// ---------------------------------------------------------------------------
// 1) deg init to 0 (incoming edges only; self loop handled analytically)
__global__ void k_init_deg(int N) {
    int i = blockIdx.x * blockDim.x + threadIdx.x;
    if (i < N) g_deg[i] = 0;
}

// 2) count incoming edges per dst  (edge_index delivered as int32)
__global__ void k_deg(const int* __restrict__ ei, int E, int N) {
    int e = blockIdx.x * blockDim.x + threadIdx.x;
    if (e < E) {
        int dst = ei[E + e];
        if ((unsigned)dst < (unsigned)N)   // safety: never fault
            atomicAdd(&g_deg[dst], 1);
    }
}

// 3) single-block exclusive scan of deg -> g_off, g_cur
__global__ void k_scan(int N) {
    __shared__ int sums[1024];
    int t = threadIdx.x;
    int chunk = (N + 1023) / 1024;
    int s0 = t * chunk;
    int s1 = min(s0 + chunk, N);
    int sum = 0;
    for (int i = s0; i < s1; i++) sum += g_deg[i];
    sums[t] = sum;
    __syncthreads();
    // Hillis-Steele inclusive scan over 1024 partials
    for (int off = 1; off < 1024; off <<= 1) {
        int v = (t >= off) ? sums[t - off] : 0;
        __syncthreads();
        sums[t] += v;
        __syncthreads();
    }
    int run = sums[t] - sum;   // exclusive prefix for this thread's chunk
    for (int i = s0; i < s1; i++) {
        g_off[i] = run;
        g_cur[i] = run;
        run += g_deg[i];
    }
    if (t == 1023) g_off[N] = sums[1023];
}

__global__ void k_dinv(int N) {
    int i = blockIdx.x * blockDim.x + threadIdx.x;
    if (i < N) g_dinv[i] = rsqrtf((float)(g_deg[i] + 1));
}

// 4) fill CSR: src list grouped by dst
__global__ void k_fill(const int* __restrict__ ei, int E, int N) {
    int e = blockIdx.x * blockDim.x + threadIdx.x;
    if (e < E) {
        int src = ei[e];
        int dst = ei[E + e];
        if ((unsigned)dst < (unsigned)N && (unsigned)src < (unsigned)N) {
            int pos = atomicAdd(&g_cur[dst], 1);
            if ((unsigned)pos < (unsigned)E_MAX) g_srcs[pos] = src;
        }
    }
}

// ---------------------------------------------------------------------------
// 5) SGEMM: H[M,128] = X[M,128] * W[128,128]
//    BM=128, BN=128, BK=8, 256 threads, 8x8 micro-tile.
__global__ void k_gemm(const float* __restrict__ X, const float* __restrict__ W,
                       int M) {
    __shared__ float As[8][128];   // [k][row]
    __shared__ float Bs[8][128];   // [k][col]

    const int tid = threadIdx.x;
    const int block_row = blockIdx.x * 128;
    const int tr = tid >> 4;       // 0..15
    const int tc = tid & 15;       // 0..15

    float acc[8][8];
#pragma unroll
    for (int i = 0; i < 8; i++)
#pragma unroll
        for (int j = 0; j < 8; j++) acc[i][j] = 0.f;

    for (int k0 = 0; k0 < 128; k0 += 8) {
        {
            int row = tid >> 1;                 // 0..127
            int kc  = (tid & 1) * 4;            // 0 or 4
            int grow = block_row + row;
            float4 v = make_float4(0.f, 0.f, 0.f, 0.f);
            if (grow < M)
                v = *reinterpret_cast<const float4*>(X + (size_t)grow * CH + k0 + kc);
            As[kc + 0][row] = v.x;
            As[kc + 1][row] = v.y;
            As[kc + 2][row] = v.z;
            As[kc + 3][row] = v.w;
        }
        {
            int row = tid >> 5;                 // 0..7
            int c4  = (tid & 31) * 4;           // 0..124
            float4 v = *reinterpret_cast<const float4*>(W + (size_t)(k0 + row) * CH + c4);
            *reinterpret_cast<float4*>(&Bs[row][c4]) = v;
        }
        __syncthreads();

#pragma unroll
        for (int k = 0; k < 8; k++) {
            float a[8], b[8];
#pragma unroll
            for (int i = 0; i < 8; i++) a[i] = As[k][tr * 8 + i];
#pragma unroll
            for (int j = 0; j < 8; j++) b[j] = Bs[k][tc * 8 + j];
#pragma unroll
            for (int i = 0; i < 8; i++)
#pragma unroll
                for (int j = 0; j < 8; j++) acc[i][j] = fmaf(a[i], b[j], acc[i][j]);
        }
        __syncthreads();
    }

#pragma unroll
    for (int i = 0; i < 8; i++) {
        int grow = block_row + tr * 8 + i;
        if (grow < M) {
            float* hp = g_h + (size_t)grow * CH + tc * 8;
#pragma unroll
            for (int j = 0; j < 8; j += 4) {
                float4 v = make_float4(acc[i][j], acc[i][j + 1], acc[i][j + 2], acc[i][j + 3]);
                *reinterpret_cast<float4*>(hp + j) = v;
            }
        }
    }
}

// ---------------------------------------------------------------------------
// 6) Gather per dst node (one warp per node): self-loop + neighbors + bias + PReLU
__global__ void k_gather(const float* __restrict__ bias,
                         const float* __restrict__ pw,
                         float* __restrict__ out, int N) {
    int gtid = blockIdx.x * blockDim.x + threadIdx.x;
    int node = gtid >> 5;
    int lane = gtid & 31;
    if (node >= N) return;

    float dn = g_dinv[node];
    const float4* hrow = reinterpret_cast<const float4*>(g_h + (size_t)node * CH);
    float4 hv = hrow[lane];
    float ws = dn * dn;                      // self-loop weight
    float4 acc;
    acc.x = hv.x * ws; acc.y = hv.y * ws; acc.z = hv.z * ws; acc.w = hv.w * ws;

    int s = g_off[node];
    int e = g_off[node + 1];
    for (int i = s; i < e; i++) {
        int src = g_srcs[i];
        float w = g_dinv[src] * dn;
        float4 h = reinterpret_cast<const float4*>(g_h + (size_t)src * CH)[lane];
        acc.x = fmaf(h.x, w, acc.x);
        acc.y = fmaf(h.y, w, acc.y);
        acc.z = fmaf(h.z, w, acc.z);
        acc.w = fmaf(h.w, w, acc.w);
    }

    float4 bb = reinterpret_cast<const float4*>(bias)[lane];
    acc.x += bb.x; acc.y += bb.y; acc.z += bb.z; acc.w += bb.w;

    float4 p = reinterpret_cast<const float4*>(pw)[lane];
    acc.x = acc.x >= 0.f ? acc.x : p.x * acc.x;
    acc.y = acc.y >= 0.f ? acc.y : p.y * acc.y;
    acc.z = acc.z >= 0.f ? acc.z : p.z * acc.z;
    acc.w = acc.w >= 0.f ? acc.w : p.w * acc.w;

    reinterpret_cast<float4*>(out + (size_t)node * CH)[lane] = acc;
}

// ---------------------------------------------------------------------------
extern "C" void kernel_launch(void* const* d_in, const int* in_sizes, int n_in,
                              void* d_out, int out_size) {
    const float* x  = (const float*)d_in[0];
    const int*   ei = (const int*)d_in[1];      // int64 in reference -> int32 on device
    const float* W  = (const float*)d_in[2];
    const float* b  = (const float*)d_in[3];
    const float* pw = (const float*)d_in[4];
    float* out = (float*)d_out;

    const int N = in_sizes[0] / CH;         // 100000
    const int E = in_sizes[1] / 2;          // 600000

    const int T = 256;

    k_init_deg<<<(N + T - 1) / T, T>>>(N);
    k_deg<<<(E + T - 1) / T, T>>>(ei, E, N);
    k_scan<<<1, 1024>>>(N);
    k_dinv<<<(N + T - 1) / T, T>>>(N);
    k_fill<<<(E + T - 1) / T, T>>>(ei, E, N);

    k_gemm<<<(N + 127) / 128, 256>>>(x, W, N);

    long long gthreads = (long long)N * 32;
    k_gather<<<(int)((gthreads + T - 1) / T), T>>>(b, pw, out, N);
}